// round 13
// baseline (speedup 1.0000x reference)
#include <cuda_runtime.h>
#include <cuda_fp16.h>
#include <cstdint>

// out = x @ (Wv@Wo) + (bv@Wo + bo)   (algebraic collapse, validated r1)
// SINGLE fused launch:
//   bids [0,64):    combine  Wc=Wv@Wo via HMMA -> g_Bhi (fp16, [n][k])
//   bids [64,72):   bc = bv@Wo + bo
//   bids [72,200):  convert  x -> fp16 per (m-block, k-chunk), releasing flags
//   bids [200,712): GEMM CTAs, pipelined behind convert via per-chunk flags
// rel_err 4.147e-4 measured (same numerics as r12).

#define D 512
#define MTOK 16384

__device__ __half g_Ahi[MTOK * D];  // x fp16
__device__ __half g_Bhi[D * D];     // WcT fp16 [n][k]
__device__ float g_bc[D];
__device__ int g_flagA[(MTOK / 128) * 16];  // per (m-block, k-chunk)
__device__ int g_combine_done = 0;
__device__ int g_fin = 0;

#define N_COMBINE 64
#define N_BC 8
#define N_PROD (N_COMBINE + N_BC)   // 72

// ───────────────────────── helpers ─────────────────────────
__device__ __forceinline__ uint32_t smem_u32(const void* p) {
    uint32_t a;
    asm("{ .reg .u64 t; cvta.to.shared.u64 t, %1; cvt.u32.u64 %0, t; }"
        : "=r"(a) : "l"(p));
    return a;
}
__device__ __forceinline__ void cp16(uint32_t dst, const void* src) {
    asm volatile("cp.async.cg.shared.global [%0], [%1], 16;"
                 :: "r"(dst), "l"(src) : "memory");
}
__device__ __forceinline__ void cp_commit() {
    asm volatile("cp.async.commit_group;" ::: "memory");
}
template <int N>
__device__ __forceinline__ void cp_wait() {
    asm volatile("cp.async.wait_group %0;" :: "n"(N) : "memory");
}
__device__ __forceinline__ void ldsm_x4(uint32_t (&r)[4], uint32_t addr) {
    asm volatile("ldmatrix.sync.aligned.m8n8.x4.shared.b16 {%0,%1,%2,%3}, [%4];"
                 : "=r"(r[0]), "=r"(r[1]), "=r"(r[2]), "=r"(r[3]) : "r"(addr));
}
__device__ __forceinline__ void mma_f16(float (&d)[4], const uint32_t (&a)[4],
                                        uint32_t b0, uint32_t b1) {
    asm volatile(
        "mma.sync.aligned.m16n8k16.row.col.f32.f16.f16.f32 "
        "{%0,%1,%2,%3}, {%4,%5,%6,%7}, {%8,%9}, {%0,%1,%2,%3};"
        : "+f"(d[0]), "+f"(d[1]), "+f"(d[2]), "+f"(d[3])
        : "r"(a[0]), "r"(a[1]), "r"(a[2]), "r"(a[3]), "r"(b0), "r"(b1));
}
__device__ __forceinline__ int ld_acq(const int* p) {
    int v;
    asm volatile("ld.acquire.gpu.global.b32 %0, [%1];" : "=r"(v) : "l"(p) : "memory");
    return v;
}

// ───────────── geometry ─────────────
#define PROWB 80
#define PTILE (64 * PROWB)
#define PSTAGE (2 * PTILE)

#define BM 128
#define BN 128
#define BKK 32
#define ROWB 80
#define OP_TILE (128 * ROWB)
#define STAGE_B (2 * OP_TILE)
#define NSTAGE 4
#define SMEM_TOTAL (NSTAGE * STAGE_B)   // 81920 B
#define NKB (D / BKK)                   // 16

__global__ __launch_bounds__(256, 2)
void fused_kernel(const float* __restrict__ x,
                  const float* __restrict__ Wv, const float* __restrict__ Wo,
                  const float* __restrict__ bv, const float* __restrict__ bo,
                  float* __restrict__ out, int nconv, int n_gemm)
{
    extern __shared__ char smem[];
    const int b = blockIdx.x;
    const int tid = threadIdx.x;

    // ═════════ combine: 64x64 tile of Wc = Wv@Wo via HMMA ═════════
    if (b < N_COMBINE) {
        char* psm = smem;
        const uint32_t sbase = smem_u32(psm);
        const int lane = tid & 31;
        const int wid = tid >> 5;
        const int m0 = (b >> 3) * 64;
        const int n0 = (b & 7) * 64;
        const int wm = (wid >> 2) * 32;
        const int wn = (wid & 3) * 16;

        float4 aR[2], bR[2];
        auto lda = [&](int kb) {
            #pragma unroll
            for (int u = 0; u < 2; u++) {
                const int ch = tid + u * 256;
                const int r = ch >> 3, c = ch & 7;
                aR[u] = __ldg(reinterpret_cast<const float4*>(
                    &Wv[(size_t)(m0 + r) * D + kb * 32 + c * 4]));
            }
        };
        auto ldb = [&](int kb) {
            #pragma unroll
            for (int u = 0; u < 2; u++) {
                const int ch = tid + u * 256;
                const int jr = ch >> 4, nc = ch & 15;
                bR[u] = __ldg(reinterpret_cast<const float4*>(
                    &Wo[(size_t)(kb * 32 + jr) * D + n0 + nc * 4]));
            }
        };
        auto sts = [&](int s) {
            char* Ab = psm + s * PSTAGE;
            char* Bb = Ab + PTILE;
            #pragma unroll
            for (int u = 0; u < 2; u++) {
                const int ch = tid + u * 256;
                {
                    const int r = ch >> 3, c = ch & 7;
                    __half2 h0 = __floats2half2_rn(aR[u].x, aR[u].y);
                    __half2 h1 = __floats2half2_rn(aR[u].z, aR[u].w);
                    uint2 v;
                    v.x = *reinterpret_cast<uint32_t*>(&h0);
                    v.y = *reinterpret_cast<uint32_t*>(&h1);
                    *reinterpret_cast<uint2*>(Ab + r * PROWB + c * 8) = v;
                }
                {
                    const int jr = ch >> 4, nc = ch & 15;
                    const float f[4] = {bR[u].x, bR[u].y, bR[u].z, bR[u].w};
                    #pragma unroll
                    for (int i = 0; i < 4; i++)
                        *reinterpret_cast<__half*>(
                            Bb + (nc * 4 + i) * PROWB + jr * 2) =
                            __float2half_rn(f[i]);
                }
            }
        };

        float acc[2][2][4] = {};
        lda(0); ldb(0); sts(0);
        lda(1); ldb(1);

        #pragma unroll
        for (int kb = 0; kb < 16; kb++) {
            __syncthreads();
            if (kb + 1 < 16) sts((kb + 1) & 1);
            if (kb + 2 < 16) { lda(kb + 2); ldb(kb + 2); }

            const uint32_t Ab = sbase + (uint32_t)(kb & 1) * PSTAGE;
            const uint32_t Bb = Ab + PTILE;
            #pragma unroll
            for (int ks = 0; ks < 2; ks++) {
                uint32_t a[2][4];
                #pragma unroll
                for (int mi = 0; mi < 2; mi++) {
                    uint32_t ra = Ab + (uint32_t)(wm + mi * 16 + (lane & 15)) * PROWB
                                + ks * 32 + ((lane >> 4) << 4);
                    ldsm_x4(a[mi], ra);
                }
                uint32_t bh[4];
                const int nl = wn + (lane & 7) + ((lane >> 4) << 3);
                uint32_t rb = Bb + (uint32_t)nl * PROWB
                            + ks * 32 + (((lane >> 3) & 1) << 4);
                ldsm_x4(bh, rb);
                #pragma unroll
                for (int mi = 0; mi < 2; mi++)
                    #pragma unroll
                    for (int ni = 0; ni < 2; ni++)
                        mma_f16(acc[mi][ni], a[mi], bh[ni * 2], bh[ni * 2 + 1]);
            }
            __syncthreads();
        }

        #pragma unroll
        for (int mi = 0; mi < 2; mi++) {
            const int row = m0 + wm + mi * 16 + (lane >> 2);
            #pragma unroll
            for (int ni = 0; ni < 2; ni++) {
                const int col = n0 + wn + ni * 8 + (lane & 3) * 2;
                g_Bhi[(size_t)col * D + row]           = __float2half_rn(acc[mi][ni][0]);
                g_Bhi[(size_t)(col + 1) * D + row]     = __float2half_rn(acc[mi][ni][1]);
                g_Bhi[(size_t)col * D + row + 8]       = __float2half_rn(acc[mi][ni][2]);
                g_Bhi[(size_t)(col + 1) * D + row + 8] = __float2half_rn(acc[mi][ni][3]);
            }
        }
        __threadfence();
        __syncthreads();
        if (tid == 0) atomicAdd(&g_combine_done, 1);
        return;
    }

    // ═════════ bc ═════════
    if (b < N_PROD) {
        float (*red)[64] = reinterpret_cast<float(*)[64]>(smem);
        const int n0 = (b - N_COMBINE) * 64;
        const int nn = tid & 63;
        const int kk = tid >> 6;
        float s = 0.f;
        #pragma unroll 16
        for (int k = kk; k < D; k += 4)
            s += bv[k] * Wo[(size_t)k * D + n0 + nn];
        red[kk][nn] = s;
        __syncthreads();
        if (tid < 64)
            g_bc[n0 + tid] = red[0][tid] + red[1][tid] + red[2][tid] + red[3][tid]
                           + bo[n0 + tid];
        __threadfence();
        __syncthreads();
        if (tid == 0) atomicAdd(&g_combine_done, 1);
        return;
    }

    // ═════════ convert: m-block (b - N_PROD), k-chunk by k-chunk ═════════
    if (b < N_PROD + nconv) {
        const int mb = b - N_PROD;
        const float* xr = x + (size_t)mb * 128 * D;
        __half* ar = g_Ahi + (size_t)mb * 128 * D;
        for (int kb = 0; kb < NKB; kb++) {
            const int k0 = kb * BKK;
            #pragma unroll
            for (int u = 0; u < 4; u++) {
                const int idx = tid + u * 256;        // 0..1023
                const int r = idx >> 3, c = idx & 7;  // 128 rows x 8 f4
                float4 v = __ldg(reinterpret_cast<const float4*>(
                    &xr[(size_t)r * D + k0 + c * 4]));
                __half2 h0 = __floats2half2_rn(v.x, v.y);
                __half2 h1 = __floats2half2_rn(v.z, v.w);
                uint2 w;
                w.x = *reinterpret_cast<uint32_t*>(&h0);
                w.y = *reinterpret_cast<uint32_t*>(&h1);
                *reinterpret_cast<uint2*>(&ar[(size_t)r * D + k0 + c * 4]) = w;
            }
            __threadfence();
            __syncthreads();
            if (tid == 0)
                asm volatile("st.release.gpu.global.b32 [%0], %1;"
                             :: "l"(&g_flagA[mb * NKB + kb]), "r"(1) : "memory");
        }
        return;
    }

    // ═════════ GEMM CTA ═════════
    {
        const uint32_t sb = smem_u32(smem);
        const int lane = tid & 31;
        const int wid = tid >> 5;
        const int c = b - N_PROD - nconv;
        const int n0 = (c & 3) * BN;    // n fast: 4 CTAs share an A tile
        const int mb = c >> 2;
        const int m0 = mb * BM;
        const int wm = (wid >> 2) * 64;
        const int wn = (wid & 3) * 32;

        auto ldab = [&](int kb, int s) {
            const uint32_t base = sb + (uint32_t)s * STAGE_B;
            const int k0 = kb * BKK;
            #pragma unroll
            for (int u = 0; u < 2; u++) {
                const int ch = tid + u * 256;
                const int r = ch >> 2, cc = ch & 3;
                cp16(base + r * ROWB + cc * 16,
                     &g_Ahi[(size_t)(m0 + r) * D + k0 + cc * 8]);
                cp16(base + OP_TILE + r * ROWB + cc * 16,
                     &g_Bhi[(size_t)(n0 + r) * D + k0 + cc * 8]);
            }
        };
        auto waitA = [&](int kb) {
            const int* f = &g_flagA[mb * NKB + kb];
            while (ld_acq(f) == 0) __nanosleep(64);
        };

        // wait for B/bias producers (all threads; no divergence on exit)
        while (ld_acq(&g_combine_done) < N_PROD) __nanosleep(128);

        float acc[4][4][4] = {};

        waitA(0); ldab(0, 0); cp_commit();
        waitA(1); ldab(1, 1); cp_commit();
        waitA(2); ldab(2, 2); cp_commit();

        #pragma unroll
        for (int kb = 0; kb < NKB; kb++) {
            cp_wait<2>();
            __syncthreads();

            if (kb + 3 < NKB) { waitA(kb + 3); ldab(kb + 3, (kb + 3) & 3); }
            cp_commit();

            const uint32_t baseA = sb + (uint32_t)(kb & 3) * STAGE_B;
            const uint32_t baseB = baseA + OP_TILE;
            #pragma unroll
            for (int ks = 0; ks < 2; ks++) {
                uint32_t a[4][4];
                #pragma unroll
                for (int mi = 0; mi < 4; mi++) {
                    uint32_t ra = baseA + (uint32_t)(wm + mi * 16 + (lane & 15)) * ROWB
                                + ks * 32 + ((lane >> 4) << 4);
                    ldsm_x4(a[mi], ra);
                }
                uint32_t bh[2][4];
                #pragma unroll
                for (int bi = 0; bi < 2; bi++) {
                    const int nl = wn + bi * 16 + (lane & 7) + ((lane >> 4) << 3);
                    uint32_t rb = baseB + (uint32_t)nl * ROWB
                                + ks * 32 + (((lane >> 3) & 1) << 4);
                    ldsm_x4(bh[bi], rb);
                }
                #pragma unroll
                for (int mi = 0; mi < 4; mi++)
                    #pragma unroll
                    for (int ni = 0; ni < 4; ni++) {
                        const int bi = ni >> 1, p = (ni & 1) * 2;
                        mma_f16(acc[mi][ni], a[mi], bh[bi][p], bh[bi][p + 1]);
                    }
            }
        }

        // epilogue: fp32 stores + bias
        #pragma unroll
        for (int mi = 0; mi < 4; mi++) {
            const int r = m0 + wm + mi * 16 + (lane >> 2);
            #pragma unroll
            for (int ni = 0; ni < 4; ni++) {
                const int cc = n0 + wn + ni * 8 + (lane & 3) * 2;
                float2 bvv = *reinterpret_cast<const float2*>(&g_bc[cc]);
                float2 v0 = make_float2(acc[mi][ni][0] + bvv.x, acc[mi][ni][1] + bvv.y);
                float2 v1 = make_float2(acc[mi][ni][2] + bvv.x, acc[mi][ni][3] + bvv.y);
                *reinterpret_cast<float2*>(&out[(size_t)r * D + cc]) = v0;
                *reinterpret_cast<float2*>(&out[(size_t)(r + 8) * D + cc]) = v1;
            }
        }

        // deterministic self-reset by the last-finishing GEMM CTA
        __syncthreads();
        __shared__ int s_last;
        if (tid == 0) s_last = (atomicAdd(&g_fin, 1) == n_gemm - 1) ? 1 : 0;
        __syncthreads();
        if (s_last) {
            for (int i = tid; i < nconv * NKB; i += 256) g_flagA[i] = 0;
            __syncthreads();
            if (tid == 0) {
                g_combine_done = 0;
                g_fin = 0;
                __threadfence();
            }
        }
    }
}

// ───────────────────────── host ─────────────────────────
extern "C" void kernel_launch(void* const* d_in, const int* in_sizes, int n_in,
                              void* d_out, int out_size)
{
    // order: x, H, W, Wq, bq, Wk, bk, Wv, bv, Wo, bo, Woff1, boff1, Woff2, boff2
    const float* x  = (const float*)d_in[0];
    const float* Wv = (const float*)d_in[7];
    const float* bv = (const float*)d_in[8];
    const float* Wo = (const float*)d_in[9];
    const float* bo = (const float*)d_in[10];
    float* out = (float*)d_out;

    const int M = in_sizes[0] / D;        // 16384 tokens
    const int nconv = M / 128;            // 128 convert blocks
    const int n_gemm = nconv * 4;         // 512 GEMM CTAs

    static bool attr_set = false;
    if (!attr_set) {
        cudaFuncSetAttribute(fused_kernel,
                             cudaFuncAttributeMaxDynamicSharedMemorySize, SMEM_TOTAL);
        attr_set = true;
    }

    fused_kernel<<<N_PROD + nconv + n_gemm, 256, SMEM_TOTAL>>>(
        x, Wv, Wo, bv, bo, out, nconv, n_gemm);
}

// round 14
// speedup vs baseline: 1.1509x; 1.1509x over previous
#include <cuda_runtime.h>
#include <cuda_fp16.h>
#include <cstdint>

// out = x @ (Wv@Wo) + (bv@Wo + bo)   (algebraic collapse, validated r1)
// Two launches (fusion loses — r10/r13 evidence):
//   pre_kernel: HMMA combine (bids 0-63) | bc (64-71) | x->fp16 convert (72+)
//   mma_kernel: all-cp.async fp16 HMMA GEMM, BK=64, 3 stages, 8 k-iterations.

#define D 512
#define MTOK 16384

__device__ __half g_Ahi[MTOK * D]; // x fp16
__device__ __half g_Bhi[D * D];    // WcT fp16  [n][k]
__device__ float g_bc[D];

// ───────────────────────── helpers ─────────────────────────
__device__ __forceinline__ uint32_t smem_u32(const void* p) {
    uint32_t a;
    asm("{ .reg .u64 t; cvta.to.shared.u64 t, %1; cvt.u32.u64 %0, t; }"
        : "=r"(a) : "l"(p));
    return a;
}
__device__ __forceinline__ void cp16(uint32_t dst, const void* src) {
    asm volatile("cp.async.cg.shared.global [%0], [%1], 16;"
                 :: "r"(dst), "l"(src) : "memory");
}
__device__ __forceinline__ void cp_commit() {
    asm volatile("cp.async.commit_group;" ::: "memory");
}
template <int N>
__device__ __forceinline__ void cp_wait() {
    asm volatile("cp.async.wait_group %0;" :: "n"(N) : "memory");
}
__device__ __forceinline__ void ldsm_x4(uint32_t (&r)[4], uint32_t addr) {
    asm volatile("ldmatrix.sync.aligned.m8n8.x4.shared.b16 {%0,%1,%2,%3}, [%4];"
                 : "=r"(r[0]), "=r"(r[1]), "=r"(r[2]), "=r"(r[3]) : "r"(addr));
}
__device__ __forceinline__ void mma_f16(float (&d)[4], const uint32_t (&a)[4],
                                        uint32_t b0, uint32_t b1) {
    asm volatile(
        "mma.sync.aligned.m16n8k16.row.col.f32.f16.f16.f32 "
        "{%0,%1,%2,%3}, {%4,%5,%6,%7}, {%8,%9}, {%0,%1,%2,%3};"
        : "+f"(d[0]), "+f"(d[1]), "+f"(d[2]), "+f"(d[3])
        : "r"(a[0]), "r"(a[1]), "r"(a[2]), "r"(a[3]), "r"(b0), "r"(b1));
}

// ───────────── pre-kernel (unchanged from r12, best-known) ─────────────
#define PROWB 80
#define PTILE (64 * PROWB)
#define PSTAGE (2 * PTILE)
#define N_COMBINE 64
#define N_BC 8
#define N_PRE (N_COMBINE + N_BC)      // 72
#define N_CONV (MTOK * D / 2048)      // 4096

__global__ __launch_bounds__(256)
void pre_kernel(const float* __restrict__ x,
                const float* __restrict__ Wv, const float* __restrict__ Wo,
                const float* __restrict__ bv, const float* __restrict__ bo)
{
    const int b = blockIdx.x;
    const int tid = threadIdx.x;

    if (b >= N_PRE) {
        // ---- convert: x -> fp16 ----
        size_t i = ((size_t)(b - N_PRE) * 256 + tid) * 8;
        float4 v0 = *reinterpret_cast<const float4*>(x + i);
        float4 v1 = *reinterpret_cast<const float4*>(x + i + 4);
        __half2 h[4];
        h[0] = __floats2half2_rn(v0.x, v0.y);
        h[1] = __floats2half2_rn(v0.z, v0.w);
        h[2] = __floats2half2_rn(v1.x, v1.y);
        h[3] = __floats2half2_rn(v1.z, v1.w);
        *reinterpret_cast<uint4*>(&g_Ahi[i]) = *reinterpret_cast<uint4*>(h);
        return;
    }

    if (b < N_COMBINE) {
        // ---- combine: 64x64 tile of Wc = Wv@Wo via HMMA ----
        __shared__ char psm[2 * PSTAGE];
        const uint32_t sbase = smem_u32(psm);
        const int lane = tid & 31;
        const int wid = tid >> 5;
        const int m0 = (b >> 3) * 64;
        const int n0 = (b & 7) * 64;
        const int wm = (wid >> 2) * 32;
        const int wn = (wid & 3) * 16;

        float4 aR[2], bR[2];
        auto lda = [&](int kb) {
            #pragma unroll
            for (int u = 0; u < 2; u++) {
                const int ch = tid + u * 256;
                const int r = ch >> 3, c = ch & 7;
                aR[u] = __ldg(reinterpret_cast<const float4*>(
                    &Wv[(size_t)(m0 + r) * D + kb * 32 + c * 4]));
            }
        };
        auto ldb = [&](int kb) {
            #pragma unroll
            for (int u = 0; u < 2; u++) {
                const int ch = tid + u * 256;
                const int jr = ch >> 4, nc = ch & 15;
                bR[u] = __ldg(reinterpret_cast<const float4*>(
                    &Wo[(size_t)(kb * 32 + jr) * D + n0 + nc * 4]));
            }
        };
        auto sts = [&](int s) {
            char* Ab = psm + s * PSTAGE;
            char* Bb = Ab + PTILE;
            #pragma unroll
            for (int u = 0; u < 2; u++) {
                const int ch = tid + u * 256;
                {
                    const int r = ch >> 3, c = ch & 7;
                    __half2 h0 = __floats2half2_rn(aR[u].x, aR[u].y);
                    __half2 h1 = __floats2half2_rn(aR[u].z, aR[u].w);
                    uint2 v;
                    v.x = *reinterpret_cast<uint32_t*>(&h0);
                    v.y = *reinterpret_cast<uint32_t*>(&h1);
                    *reinterpret_cast<uint2*>(Ab + r * PROWB + c * 8) = v;
                }
                {
                    const int jr = ch >> 4, nc = ch & 15;
                    const float f[4] = {bR[u].x, bR[u].y, bR[u].z, bR[u].w};
                    #pragma unroll
                    for (int i = 0; i < 4; i++)
                        *reinterpret_cast<__half*>(
                            Bb + (nc * 4 + i) * PROWB + jr * 2) =
                            __float2half_rn(f[i]);
                }
            }
        };

        float acc[2][2][4] = {};
        lda(0); ldb(0); sts(0);
        lda(1); ldb(1);

        #pragma unroll
        for (int kb = 0; kb < 16; kb++) {
            __syncthreads();
            if (kb + 1 < 16) sts((kb + 1) & 1);
            if (kb + 2 < 16) { lda(kb + 2); ldb(kb + 2); }

            const uint32_t Ab = sbase + (uint32_t)(kb & 1) * PSTAGE;
            const uint32_t Bb = Ab + PTILE;
            #pragma unroll
            for (int ks = 0; ks < 2; ks++) {
                uint32_t a[2][4];
                #pragma unroll
                for (int mi = 0; mi < 2; mi++) {
                    uint32_t ra = Ab + (uint32_t)(wm + mi * 16 + (lane & 15)) * PROWB
                                + ks * 32 + ((lane >> 4) << 4);
                    ldsm_x4(a[mi], ra);
                }
                uint32_t bh[4];
                const int nl = wn + (lane & 7) + ((lane >> 4) << 3);
                uint32_t rb = Bb + (uint32_t)nl * PROWB
                            + ks * 32 + (((lane >> 3) & 1) << 4);
                ldsm_x4(bh, rb);
                #pragma unroll
                for (int mi = 0; mi < 2; mi++)
                    #pragma unroll
                    for (int ni = 0; ni < 2; ni++)
                        mma_f16(acc[mi][ni], a[mi], bh[ni * 2], bh[ni * 2 + 1]);
            }
            __syncthreads();
        }

        #pragma unroll
        for (int mi = 0; mi < 2; mi++) {
            const int row = m0 + wm + mi * 16 + (lane >> 2);
            #pragma unroll
            for (int ni = 0; ni < 2; ni++) {
                const int col = n0 + wn + ni * 8 + (lane & 3) * 2;
                g_Bhi[(size_t)col * D + row]           = __float2half_rn(acc[mi][ni][0]);
                g_Bhi[(size_t)(col + 1) * D + row]     = __float2half_rn(acc[mi][ni][1]);
                g_Bhi[(size_t)col * D + row + 8]       = __float2half_rn(acc[mi][ni][2]);
                g_Bhi[(size_t)(col + 1) * D + row + 8] = __float2half_rn(acc[mi][ni][3]);
            }
        }
        return;
    }

    // ---- bc ----
    {
        __shared__ float red[4][64];
        const int n0 = (b - N_COMBINE) * 64;
        const int nn = tid & 63;
        const int kk = tid >> 6;
        float s = 0.f;
        #pragma unroll 16
        for (int k = kk; k < D; k += 4)
            s += bv[k] * Wo[(size_t)k * D + n0 + nn];
        red[kk][nn] = s;
        __syncthreads();
        if (tid < 64)
            g_bc[n0 + tid] = red[0][tid] + red[1][tid] + red[2][tid] + red[3][tid]
                           + bo[n0 + tid];
    }
}

// ───────────── main GEMM: all-cp.async fp16 HMMA, BK=64 ─────────────
// CTA 128x128, 8 k-iterations, 3 stages, one barrier per iter.
#define BM 128
#define BN 128
#define BKK 64
#define ROWB 144                      // 128B data + 16B pad (conflict-free ldsm)
#define OP_TILE (128 * ROWB)          // 18432 B per operand
#define STAGE_B (2 * OP_TILE)         // 36864 B (A + B)
#define NSTAGE 3
#define SMEM_TOTAL (NSTAGE * STAGE_B) // 110592 B
#define NKB (D / BKK)                 // 8

__global__ __launch_bounds__(256, 2)
void mma_kernel(const __half* __restrict__ Ahi,
                const __half* __restrict__ Bhi,
                const float* __restrict__ bc, float* __restrict__ out)
{
    extern __shared__ char smem[];
    const uint32_t sb = smem_u32(smem);
    const int tid = threadIdx.x;
    const int lane = tid & 31;
    const int wid = tid >> 5;
    const int n0 = blockIdx.x * BN;   // n fast: 4 CTAs share an A tile
    const int m0 = blockIdx.y * BM;
    const int wm = (wid >> 2) * 64;
    const int wn = (wid & 3) * 32;

    auto ldab = [&](int kb, int s) {
        const uint32_t base = sb + (uint32_t)s * STAGE_B;
        const int k0 = kb * BKK;
        #pragma unroll
        for (int u = 0; u < 4; u++) {
            const int ch = tid + u * 256;        // 0..1023
            const int r = ch >> 3, c = ch & 7;   // 128 rows x 8 16B-chunks
            cp16(base + r * ROWB + c * 16,
                 Ahi + (size_t)(m0 + r) * D + k0 + c * 8);
            cp16(base + OP_TILE + r * ROWB + c * 16,
                 Bhi + (size_t)(n0 + r) * D + k0 + c * 8);
        }
    };

    float acc[4][4][4] = {};

    // prologue: stages 0,1
    ldab(0, 0); cp_commit();
    ldab(1, 1); cp_commit();

    #pragma unroll
    for (int kb = 0; kb < NKB; kb++) {
        if (kb < NKB - 1) cp_wait<1>(); else cp_wait<0>();
        __syncthreads();

        // prefetch kb+2 into stage (kb+2)%3 (last read in iter kb-1, pre-barrier)
        if (kb + 2 < NKB) ldab(kb + 2, (kb + 2) % 3);
        cp_commit();

        const uint32_t baseA = sb + (uint32_t)(kb % 3) * STAGE_B;
        const uint32_t baseB = baseA + OP_TILE;
        #pragma unroll
        for (int ks = 0; ks < 4; ks++) {
            uint32_t a[4][4];
            #pragma unroll
            for (int mi = 0; mi < 4; mi++) {
                uint32_t ra = baseA + (uint32_t)(wm + mi * 16 + (lane & 15)) * ROWB
                            + ks * 32 + ((lane >> 4) << 4);
                ldsm_x4(a[mi], ra);
            }
            uint32_t bh[2][4];
            #pragma unroll
            for (int bi = 0; bi < 2; bi++) {
                const int nl = wn + bi * 16 + (lane & 7) + ((lane >> 4) << 3);
                uint32_t rb = baseB + (uint32_t)nl * ROWB
                            + ks * 32 + (((lane >> 3) & 1) << 4);
                ldsm_x4(bh[bi], rb);
            }
            #pragma unroll
            for (int mi = 0; mi < 4; mi++)
                #pragma unroll
                for (int ni = 0; ni < 4; ni++) {
                    const int bi = ni >> 1, p = (ni & 1) * 2;
                    mma_f16(acc[mi][ni], a[mi], bh[bi][p], bh[bi][p + 1]);
                }
        }
    }

    // epilogue: fp32 stores + bias
    #pragma unroll
    for (int mi = 0; mi < 4; mi++) {
        const int r = m0 + wm + mi * 16 + (lane >> 2);
        #pragma unroll
        for (int ni = 0; ni < 4; ni++) {
            const int c = n0 + wn + ni * 8 + (lane & 3) * 2;
            float2 bv = *reinterpret_cast<const float2*>(&bc[c]);
            float2 v0 = make_float2(acc[mi][ni][0] + bv.x, acc[mi][ni][1] + bv.y);
            float2 v1 = make_float2(acc[mi][ni][2] + bv.x, acc[mi][ni][3] + bv.y);
            *reinterpret_cast<float2*>(&out[(size_t)r * D + c]) = v0;
            *reinterpret_cast<float2*>(&out[(size_t)(r + 8) * D + c]) = v1;
        }
    }
}

// ───────────────────────── host ─────────────────────────
extern "C" void kernel_launch(void* const* d_in, const int* in_sizes, int n_in,
                              void* d_out, int out_size)
{
    // order: x, H, W, Wq, bq, Wk, bk, Wv, bv, Wo, bo, Woff1, boff1, Woff2, boff2
    const float* x  = (const float*)d_in[0];
    const float* Wv = (const float*)d_in[7];
    const float* bv = (const float*)d_in[8];
    const float* Wo = (const float*)d_in[9];
    const float* bo = (const float*)d_in[10];
    float* out = (float*)d_out;

    const int M = in_sizes[0] / D;   // 16384 tokens

    __half *ahi, *bhi;
    float* bc;
    cudaGetSymbolAddress((void**)&ahi, g_Ahi);
    cudaGetSymbolAddress((void**)&bhi, g_Bhi);
    cudaGetSymbolAddress((void**)&bc,  g_bc);

    static bool attr_set = false;
    if (!attr_set) {
        cudaFuncSetAttribute(mma_kernel,
                             cudaFuncAttributeMaxDynamicSharedMemorySize, SMEM_TOTAL);
        attr_set = true;
    }

    pre_kernel<<<N_PRE + N_CONV, 256>>>(x, Wv, Wo, bv, bo);
    mma_kernel<<<dim3(D / BN, M / BM), 256, SMEM_TOTAL>>>(ahi, bhi, bc, out);
}